// round 16
// baseline (speedup 1.0000x reference)
#include <cuda_runtime.h>
#include <cuda_fp16.h>
#include <cstdint>

#define D      1024
#define NTOK   2048
#define NB     4
#define MTOT   8192
#define NSPLIT 8

#define BK 64
#define NCH (D / BK)                // 16
#define BLK_BYTES 16384
#define A_BYTES   BLK_BYTES
#define STAGE_BYTES (2 * BLK_BYTES)
#define NSTAGE 3
#define DSM (NSTAGE * STAGE_BYTES + 1024)
#define SWZ(x) ((x) ^ (((x) >> 3) & 0x70))
#define CLOGF 0.045084220027780106f

#define T_MGEMM 64
#define T_PROJ  512
#define T_ATTN  512
#define T_TOTAL (T_MGEMM + T_PROJ + T_ATTN)   // 1088
#define PERSIST_CTAS 296

// Block layout for a [R x 1024] fp16 matrix (R multiple of 128):
//   byte(row, col) = ((row>>7)*16 + (col>>6))*16384 + SWZ((row&127)*128 + (col&63)*2)

// ---- scratch (device globals: allocation-free rule) ----
__device__ __half g_xb[MTOT * D];
__device__ __half g_wqT[D * D];
__device__ __half g_wkT[D * D];
__device__ __half g_mt[D * D];
__device__ __half g_y[MTOT * D];
__device__ float  g_u[D];
__device__ float  g_cvec[D];
__device__ float  g_c;
__device__ float2 g_sc[MTOT];
__device__ float2 g_part[MTOT * NSPLIT];
__device__ unsigned int g_ctr;
__device__ unsigned int g_fmt[8];     // Mt row-tile done counts (jt)
__device__ unsigned int g_fy[64];     // y row-tile done counts (rt)

// ============================ PTX helpers ============================
__device__ __forceinline__ uint32_t smem_u32(const void* p) {
    uint32_t a;
    asm("{ .reg .u64 t; cvta.to.shared.u64 t, %1; cvt.u32.u64 %0, t; }"
        : "=r"(a) : "l"(p));
    return a;
}
__device__ __forceinline__ uint32_t h2_bits(__half2 h) {
    union { __half2 h; uint32_t u; } cv;
    cv.h = h;
    return cv.u;
}
__device__ __forceinline__ void mbar_init(uint32_t bar, uint32_t cnt) {
    asm volatile("mbarrier.init.shared.b64 [%0], %1;" :: "r"(bar), "r"(cnt) : "memory");
}
__device__ __forceinline__ void expect_tx(uint32_t bar, uint32_t bytes) {
    asm volatile("mbarrier.arrive.expect_tx.shared.b64 _, [%0], %1;"
                 :: "r"(bar), "r"(bytes) : "memory");
}
__device__ __forceinline__ void bulk_g2s(uint32_t dst, const void* src,
                                         uint32_t bytes, uint32_t bar) {
    asm volatile(
        "cp.async.bulk.shared::cluster.global.mbarrier::complete_tx::bytes "
        "[%0], [%1], %2, [%3];"
        :: "r"(dst), "l"(src), "r"(bytes), "r"(bar) : "memory");
}
__device__ __forceinline__ void bar_wait(uint32_t bar, uint32_t parity) {
    asm volatile(
        "{\n\t.reg .pred P;\n"
        "W%=:\n\t"
        "mbarrier.try_wait.parity.shared.b64 P, [%0], %1;\n\t"
        "@!P bra W%=;\n\t}"
        :: "r"(bar), "r"(parity) : "memory");
}
#define FENCE_ASYNC() asm volatile("fence.proxy.async.shared::cta;" ::: "memory")
#define FENCE_PROXY_ALL() asm volatile("fence.proxy.async;" ::: "memory")

__device__ __forceinline__ void ldsm4(uint32_t* d, uint32_t addr) {
    asm volatile("ldmatrix.sync.aligned.m8n8.x4.shared.b16 {%0,%1,%2,%3}, [%4];"
                 : "=r"(d[0]), "=r"(d[1]), "=r"(d[2]), "=r"(d[3]) : "r"(addr));
}
__device__ __forceinline__ void mma16816(float* c, const uint32_t* a,
                                         uint32_t b0, uint32_t b1) {
    asm volatile(
        "mma.sync.aligned.m16n8k16.row.col.f32.f16.f16.f32 "
        "{%0,%1,%2,%3}, {%4,%5,%6,%7}, {%8,%9}, {%0,%1,%2,%3};"
        : "+f"(c[0]), "+f"(c[1]), "+f"(c[2]), "+f"(c[3])
        : "r"(a[0]), "r"(a[1]), "r"(a[2]), "r"(a[3]), "r"(b0), "r"(b1));
}

__device__ __forceinline__ float fexp2(float t) {
    t = fmaxf(t, -60.0f);
    float z = t + 12582912.0f;
    int   ki = __float_as_int(z);
    float n  = z - 12582912.0f;
    float f  = t - n;
    float p = 0.0013333558f;
    p = fmaf(p, f, 0.0096181291f);
    p = fmaf(p, f, 0.0555041087f);
    p = fmaf(p, f, 0.2402265070f);
    p = fmaf(p, f, 0.6931471806f);
    p = fmaf(p, f, 1.0f);
    return __int_as_float(__float_as_int(p) + (ki << 23));
}

// ============================ GEMM microkernel ============================
__device__ __forceinline__ void gemm_tile(uint32_t sbase, uint32_t mbar,
                                          const char* srcA, const char* srcB,
                                          int tid, int cnt[NSTAGE],
                                          float c[4][4][4]) {
    const int lane = tid & 31, warp = tid >> 5;
    const int mw = warp & 1, nw = warp >> 1;
    const int q2 = lane >> 3, r = lane & 7;
    const int kbh = (q2 >> 1) * 16;
    uint32_t aoff[4], boff[2];
    #pragma unroll
    for (int mt = 0; mt < 4; mt++)
        aoff[mt] = (uint32_t)((mw * 64 + mt * 16 + (q2 & 1) * 8 + r) * 128 + kbh);
    #pragma unroll
    for (int nb = 0; nb < 2; nb++)
        boff[nb] = (uint32_t)((nw * 32 + nb * 16 + (q2 & 1) * 8 + r) * 128 + kbh);

    if (tid == 0) {
        #pragma unroll
        for (int s = 0; s < NSTAGE; s++) {
            expect_tx(mbar + s * 8, 2 * BLK_BYTES);
            bulk_g2s(sbase + s * STAGE_BYTES,           srcA + s * BLK_BYTES,
                     BLK_BYTES, mbar + s * 8);
            bulk_g2s(sbase + s * STAGE_BYTES + A_BYTES, srcB + s * BLK_BYTES,
                     BLK_BYTES, mbar + s * 8);
        }
    }

    #pragma unroll 1
    for (int g = 0; g < NCH; g++) {
        int s = g % NSTAGE;
        bar_wait(mbar + s * 8, cnt[s] & 1);
        cnt[s]++;

        uint32_t sA = sbase + s * STAGE_BYTES;
        uint32_t sB = sA + A_BYTES;
        #pragma unroll
        for (int ks = 0; ks < 4; ks++) {
            int kd = ks * 32;
            uint32_t a[4][4], b[2][4];
            #pragma unroll
            for (int mt = 0; mt < 4; mt++) ldsm4(a[mt], sA + SWZ(aoff[mt] + kd));
            #pragma unroll
            for (int nb = 0; nb < 2; nb++) ldsm4(b[nb], sB + SWZ(boff[nb] + kd));
            #pragma unroll
            for (int mt = 0; mt < 4; mt++)
                #pragma unroll
                for (int nt = 0; nt < 4; nt++)
                    mma16816(c[mt][nt], a[mt],
                             b[nt >> 1][nt & 1], b[nt >> 1][(nt & 1) + 2]);
        }
        __syncthreads();
        if (tid == 0 && g + NSTAGE < NCH) {
            expect_tx(mbar + s * 8, 2 * BLK_BYTES);
            bulk_g2s(sA,           srcA + (size_t)(g + NSTAGE) * BLK_BYTES,
                     BLK_BYTES, mbar + s * 8);
            bulk_g2s(sA + A_BYTES, srcB + (size_t)(g + NSTAGE) * BLK_BYTES,
                     BLK_BYTES, mbar + s * 8);
        }
    }
}

__device__ __forceinline__ void mbar_setup(uint32_t mbar, int tid) {
    if (tid == 0) {
        #pragma unroll
        for (int s = 0; s < NSTAGE; s++) mbar_init(mbar + s * 8, 1);
        FENCE_ASYNC();
    }
    __syncthreads();
}

// fp16-blocked epilogue write: C fragment -> blocked dst (no bias)
__device__ __forceinline__ void epi_write(char* out, int rowtile, int coltile,
                                          int tid, float c[4][4][4]) {
    const int lane = tid & 31, warp = tid >> 5;
    const int mw = warp & 1, nw = warp >> 1;
    const int gq = lane >> 2, tg = lane & 3;
    #pragma unroll
    for (int mt = 0; mt < 4; mt++) {
        int rowL = mw * 64 + mt * 16 + gq;
        #pragma unroll
        for (int nt = 0; nt < 4; nt++) {
            int colL = nw * 32 + nt * 8 + 2 * tg;
            int col  = coltile * 128 + colL;
            float* cc = c[mt][nt];
            size_t blk = ((size_t)(rowtile * 16 + (col >> 6))) * BLK_BYTES;
            uint32_t cb = (uint32_t)((col & 63) * 2);
            *(__half2*)(out + blk + SWZ((uint32_t)( rowL      * 128) + cb)) =
                __floats2half2_rn(cc[0], cc[1]);
            *(__half2*)(out + blk + SWZ((uint32_t)((rowL + 8) * 128) + cb)) =
                __floats2half2_rn(cc[2], cc[3]);
        }
    }
}

// spin until *flag >= val (tid 0), then CTA-wide sync + proxy fence
__device__ __forceinline__ void wait_flag(unsigned int* flag, unsigned int val,
                                          int tid) {
    if (tid == 0) {
        while (atomicAdd(flag, 0u) < val) __nanosleep(128);
        FENCE_PROXY_ALL();
    }
    __syncthreads();
}

// ============================ small kernels ============================
__global__ void conv_x_kernel(const float* __restrict__ x) {
    size_t gid = (size_t)blockIdx.x * 256 + threadIdx.x;
    size_t e = gid * 8;
    int row = (int)(e >> 10);
    int col = (int)(e & 1023);
    const float4* s4 = (const float4*)(x + e);
    float4 v0 = s4[0], v1 = s4[1];
    uint4 o;
    o.x = h2_bits(__floats2half2_rn(v0.x, v0.y));
    o.y = h2_bits(__floats2half2_rn(v0.z, v0.w));
    o.z = h2_bits(__floats2half2_rn(v1.x, v1.y));
    o.w = h2_bits(__floats2half2_rn(v1.z, v1.w));
    uint32_t inblk = SWZ((uint32_t)((row & 127) * 128 + (col & 63) * 2));
    size_t byte = ((size_t)((row >> 7) * 16 + (col >> 6))) * BLK_BYTES + inblk;
    *(uint4*)((char*)g_xb + byte) = o;
}

__global__ void conv_wT_kernel(const float* __restrict__ Wq,
                               const float* __restrict__ Wk) {
    int g = blockIdx.x * 256 + threadIdx.x;
    const float* src = (g < 131072) ? Wq : Wk;
    char* dst        = (g < 131072) ? (char*)g_wqT : (char*)g_wkT;
    int gm = g & 131071;
    int i  = gm & 1023;
    int ob = (gm >> 10) << 3;
    float v0 = src[(size_t)(ob + 0) * D + i];
    float v1 = src[(size_t)(ob + 1) * D + i];
    float v2 = src[(size_t)(ob + 2) * D + i];
    float v3 = src[(size_t)(ob + 3) * D + i];
    float v4 = src[(size_t)(ob + 4) * D + i];
    float v5 = src[(size_t)(ob + 5) * D + i];
    float v6 = src[(size_t)(ob + 6) * D + i];
    float v7 = src[(size_t)(ob + 7) * D + i];
    uint4 o;
    o.x = h2_bits(__floats2half2_rn(v0, v1));
    o.y = h2_bits(__floats2half2_rn(v2, v3));
    o.z = h2_bits(__floats2half2_rn(v4, v5));
    o.w = h2_bits(__floats2half2_rn(v6, v7));
    uint32_t inblk = SWZ((uint32_t)((i & 127) * 128 + (ob & 63) * 2));
    size_t byte = ((size_t)((i >> 7) * 16 + (ob >> 6))) * BLK_BYTES + inblk;
    *(uint4*)(dst + byte) = o;
}

__global__ void prep_u_kernel(const float* __restrict__ Wv,
                              const float* __restrict__ bv,
                              const float* __restrict__ Ww,
                              const float* __restrict__ Wk,
                              const float* __restrict__ bq) {
    if (blockIdx.x < 4) {
        int e = blockIdx.x * 256 + threadIdx.x;
        float sum = 0.f;
        #pragma unroll 8
        for (int d = 0; d < D; d++) sum = fmaf(Ww[d], Wv[d * D + e], sum);
        g_u[e] = sum;
    } else if (blockIdx.x == 4) {
        __shared__ float red[256];
        if (threadIdx.x < 64) g_fy[threadIdx.x] = 0u;
        else if (threadIdx.x < 72) g_fmt[threadIdx.x - 64] = 0u;
        else if (threadIdx.x == 72) g_ctr = 0u;
        float s = 0.f;
        for (int d = threadIdx.x; d < D; d += 256) s = fmaf(Ww[d], bv[d], s);
        red[threadIdx.x] = s;
        __syncthreads();
        for (int off = 128; off > 0; off >>= 1) {
            if (threadIdx.x < off) red[threadIdx.x] += red[threadIdx.x + off];
            __syncthreads();
        }
        if (threadIdx.x == 0) g_c = red[0];
    } else {
        int e = (blockIdx.x - 5) * 256 + threadIdx.x;
        float sum = 0.f;
        #pragma unroll 8
        for (int d = 0; d < D; d++) sum = fmaf(bq[d], Wk[d * D + e], sum);
        g_cvec[e] = sum;
    }
}

__global__ void s_kernel(const float* __restrict__ x) {
    int row  = blockIdx.x * 8 + (threadIdx.x >> 5);
    int lane = threadIdx.x & 31;
    const float4* xr = (const float4*)(x + (size_t)row * D);
    const float4* u4 = (const float4*)g_u;
    const float4* c4 = (const float4*)g_cvec;
    float su = 0.f, sc = 0.f;
    #pragma unroll
    for (int i = 0; i < 8; i++) {
        float4 a = xr[lane + i * 32];
        float4 b = u4[lane + i * 32];
        float4 cv = c4[lane + i * 32];
        su += a.x * b.x + a.y * b.y + a.z * b.z + a.w * b.w;
        sc += a.x * cv.x + a.y * cv.y + a.z * cv.z + a.w * cv.w;
    }
    #pragma unroll
    for (int off = 16; off > 0; off >>= 1) {
        su += __shfl_xor_sync(0xffffffffu, su, off);
        sc += __shfl_xor_sync(0xffffffffu, sc, off);
    }
    if (lane == 0)
        g_sc[row] = make_float2(su + g_c, sc * CLOGF - 4.0f);
}

// ============================ mega kernel ============================
// Persistent fused pipeline: mgemm (64) -> proj (512) -> attn (512) via a
// single monotonic ticket counter + per-tile done-flags. Deadlock-free:
// producer tickets are all handed out before any consumer ticket.
__global__ __launch_bounds__(256, 2)
void mega_kernel() {
    extern __shared__ char dsm[];
    __shared__ __align__(8) uint64_t s_bar[NSTAGE];
    __shared__ float2 s_sm[128];
    __shared__ float s_red[128][4][2];
    __shared__ int s_tile;

    const int tid  = threadIdx.x;
    uint32_t sbase = (smem_u32(dsm) + 1023u) & ~1023u;
    uint32_t mbar  = smem_u32(s_bar);
    mbar_setup(mbar, tid);

    const int lane = tid & 31, warp = tid >> 5;
    const int mw = warp & 1, nw = warp >> 1;
    const int gq = lane >> 2, tg = lane & 3;
    int cnt[NSTAGE] = {0, 0, 0};

    for (;;) {
        __syncthreads();
        if (tid == 0) s_tile = (int)atomicAdd(&g_ctr, 1u);
        __syncthreads();
        int t = s_tile;
        if (t >= T_TOTAL) break;

        if (t < T_MGEMM) {
            // -------- Mt tile: Mt[jt,it] = WkT(jt) x WqT(it)^T --------
            int jt = t >> 3, it = t & 7;
            float cacc[4][4][4];
            #pragma unroll
            for (int a = 0; a < 4; a++)
                #pragma unroll
                for (int b = 0; b < 4; b++)
                    #pragma unroll
                    for (int e = 0; e < 4; e++) cacc[a][b][e] = 0.f;
            gemm_tile(sbase, mbar,
                      (const char*)g_wkT + (size_t)jt * 16 * BLK_BYTES,
                      (const char*)g_wqT + (size_t)it * 16 * BLK_BYTES,
                      tid, cnt, cacc);
            epi_write((char*)g_mt, jt, it, tid, cacc);
            __threadfence();
            __syncthreads();
            if (tid == 0) atomicAdd(&g_fmt[jt], 1u);
        } else if (t < T_MGEMM + T_PROJ) {
            // -------- y tile: y(rt,ct) = xb(rt) x Mt(ct)^T --------
            int p = t - T_MGEMM;
            int rt = p >> 3, ct = p & 7;
            wait_flag(&g_fmt[ct], 8u, tid);
            float cacc[4][4][4];
            #pragma unroll
            for (int a = 0; a < 4; a++)
                #pragma unroll
                for (int b = 0; b < 4; b++)
                    #pragma unroll
                    for (int e = 0; e < 4; e++) cacc[a][b][e] = 0.f;
            gemm_tile(sbase, mbar,
                      (const char*)g_xb + (size_t)rt * 16 * BLK_BYTES,
                      (const char*)g_mt + (size_t)ct * 16 * BLK_BYTES,
                      tid, cnt, cacc);
            epi_write((char*)g_y, rt, ct, tid, cacc);
            __threadfence();
            __syncthreads();
            if (tid == 0) atomicAdd(&g_fy[rt], 1u);
        } else {
            // -------- attn tile: q-tile gqt x 256-key split --------
            int a2 = t - T_MGEMM - T_PROJ;
            int gqt = a2 >> 3, split = a2 & 7;
            int b = gqt >> 4;
            const int row0 = gqt * 128;
            wait_flag(&g_fy[gqt], 8u, tid);

            float num[4][2], den[4][2];
            #pragma unroll
            for (int mt = 0; mt < 4; mt++)
                #pragma unroll
                for (int h = 0; h < 2; h++) { num[mt][h] = 0.f; den[mt][h] = 0.f; }

            #pragma unroll 1
            for (int blk = 0; blk < 2; blk++) {
                const int kb = b * NTOK + split * 256 + blk * 128;
                if (tid < 128) s_sm[tid] = g_sc[kb + tid];
                // (gemm_tile's internal __syncthreads orders this)

                float cacc[4][4][4];
                #pragma unroll
                for (int a = 0; a < 4; a++)
                    #pragma unroll
                    for (int c = 0; c < 4; c++)
                        #pragma unroll
                        for (int e = 0; e < 4; e++) cacc[a][c][e] = 0.f;

                gemm_tile(sbase, mbar,
                          (const char*)g_y  + (size_t)gqt * 16 * BLK_BYTES,
                          (const char*)g_xb + (size_t)(kb >> 7) * 16 * BLK_BYTES,
                          tid, cnt, cacc);

                #pragma unroll
                for (int mt = 0; mt < 4; mt++)
                    #pragma unroll
                    for (int nt = 0; nt < 4; nt++) {
                        int colL = nw * 32 + nt * 8 + 2 * tg;
                        float2 sv0 = s_sm[colL], sv1 = s_sm[colL + 1];
                        float* cc = cacc[mt][nt];
                        float e0 = fexp2(fmaf(cc[0], CLOGF, sv0.y));
                        float e1 = fexp2(fmaf(cc[1], CLOGF, sv1.y));
                        float e2 = fexp2(fmaf(cc[2], CLOGF, sv0.y));
                        float e3 = fexp2(fmaf(cc[3], CLOGF, sv1.y));
                        den[mt][0] += e0 + e1;
                        den[mt][1] += e2 + e3;
                        num[mt][0] = fmaf(e0, sv0.x, fmaf(e1, sv1.x, num[mt][0]));
                        num[mt][1] = fmaf(e2, sv0.x, fmaf(e3, sv1.x, num[mt][1]));
                    }
                __syncthreads();
            }

            #pragma unroll
            for (int mt = 0; mt < 4; mt++)
                #pragma unroll
                for (int h = 0; h < 2; h++) {
                    num[mt][h] += __shfl_xor_sync(0xffffffffu, num[mt][h], 1);
                    num[mt][h] += __shfl_xor_sync(0xffffffffu, num[mt][h], 2);
                    den[mt][h] += __shfl_xor_sync(0xffffffffu, den[mt][h], 1);
                    den[mt][h] += __shfl_xor_sync(0xffffffffu, den[mt][h], 2);
                }
            if (tg == 0) {
                #pragma unroll
                for (int mt = 0; mt < 4; mt++)
                    #pragma unroll
                    for (int h = 0; h < 2; h++) {
                        int rowl = mw * 64 + mt * 16 + h * 8 + gq;
                        s_red[rowl][nw][0] = num[mt][h];
                        s_red[rowl][nw][1] = den[mt][h];
                    }
            }
            __syncthreads();
            if (tid < 128) {
                float n = 0.f, d = 0.f;
                #pragma unroll
                for (int w = 0; w < 4; w++) {
                    n += s_red[tid][w][0];
                    d += s_red[tid][w][1];
                }
                g_part[(size_t)(row0 + tid) * NSPLIT + split] = make_float2(n, d);
            }
        }
    }
}

// ============================ combine ============================
__global__ void combine_kernel(const float* __restrict__ bw,
                               float* __restrict__ out) {
    int row = blockIdx.x * 256 + threadIdx.x;
    float n = 0.f, d = 0.f;
    #pragma unroll
    for (int s = 0; s < NSPLIT; s++) {
        float2 p = g_part[(size_t)row * NSPLIT + s];
        n += p.x; d += p.y;
    }
    out[row] = n / d + bw[0];
}

// ============================ launcher ============================
extern "C" void kernel_launch(void* const* d_in, const int* in_sizes, int n_in,
                              void* d_out, int out_size) {
    const float* x  = (const float*)d_in[0];
    const float* Wq = (const float*)d_in[1];
    const float* bq = (const float*)d_in[2];
    const float* Wk = (const float*)d_in[3];
    const float* bk = (const float*)d_in[4];
    const float* Wv = (const float*)d_in[5];
    const float* bv = (const float*)d_in[6];
    const float* Ww = (const float*)d_in[7];
    const float* bw = (const float*)d_in[8];
    float* out = (float*)d_out;
    (void)bk;

    cudaFuncSetAttribute(mega_kernel,
        cudaFuncAttributeMaxDynamicSharedMemorySize, DSM);

    conv_x_kernel<<<4096, 256>>>(x);
    conv_wT_kernel<<<1024, 256>>>(Wq, Wk);
    prep_u_kernel<<<9, 256>>>(Wv, bv, Ww, Wk, bq);
    s_kernel<<<MTOT / 8, 256>>>(x);

    mega_kernel<<<PERSIST_CTAS, 256, DSM>>>();

    combine_kernel<<<MTOT / 256, 256>>>(bw, out);
}

// round 17
// speedup vs baseline: 1.0841x; 1.0841x over previous
#include <cuda_runtime.h>
#include <cuda_fp16.h>
#include <cstdint>

#define D      1024
#define NTOK   2048
#define NB     4
#define MTOT   8192
#define NSPLIT 8

#define BK 64
#define NCH (D / BK)                // 16
#define BLK_BYTES 16384
#define A_BYTES   BLK_BYTES
#define STAGE_BYTES (2 * BLK_BYTES)
#define NSTAGE 3
#define DSM (NSTAGE * STAGE_BYTES + 1024)
#define SWZ(x) ((x) ^ (((x) >> 3) & 0x70))
#define CLOGF 0.045084220027780106f

#define NPROJ_TILES 512             // y = x@Mt^T : 64 rt x 8 ct
#define NATTN_TILES 512             // 4 b x 8 split x 16 ntq
#define PERSIST_CTAS 296

// Block layout for a [R x 1024] fp16 matrix (R multiple of 128):
//   byte(row, col) = ((row>>7)*16 + (col>>6))*16384 + SWZ((row&127)*128 + (col&63)*2)

// ---- scratch (device globals: allocation-free rule) ----
__device__ __half g_xb[MTOT * D];
__device__ __half g_wqT[D * D];
__device__ __half g_wkT[D * D];
__device__ __half g_mt[D * D];
__device__ __half g_y[MTOT * D];
__device__ float  g_u[D];
__device__ float  g_cvec[D];
__device__ float  g_c;
__device__ float2 g_sc[MTOT];
__device__ float2 g_part[MTOT * NSPLIT];
__device__ unsigned int g_ctr[2];

// ============================ PTX helpers ============================
__device__ __forceinline__ uint32_t smem_u32(const void* p) {
    uint32_t a;
    asm("{ .reg .u64 t; cvta.to.shared.u64 t, %1; cvt.u32.u64 %0, t; }"
        : "=r"(a) : "l"(p));
    return a;
}
__device__ __forceinline__ uint32_t h2_bits(__half2 h) {
    union { __half2 h; uint32_t u; } cv;
    cv.h = h;
    return cv.u;
}
__device__ __forceinline__ void mbar_init(uint32_t bar, uint32_t cnt) {
    asm volatile("mbarrier.init.shared.b64 [%0], %1;" :: "r"(bar), "r"(cnt) : "memory");
}
__device__ __forceinline__ void expect_tx(uint32_t bar, uint32_t bytes) {
    asm volatile("mbarrier.arrive.expect_tx.shared.b64 _, [%0], %1;"
                 :: "r"(bar), "r"(bytes) : "memory");
}
__device__ __forceinline__ void bulk_g2s(uint32_t dst, const void* src,
                                         uint32_t bytes, uint32_t bar) {
    asm volatile(
        "cp.async.bulk.shared::cluster.global.mbarrier::complete_tx::bytes "
        "[%0], [%1], %2, [%3];"
        :: "r"(dst), "l"(src), "r"(bytes), "r"(bar) : "memory");
}
__device__ __forceinline__ void bar_wait(uint32_t bar, uint32_t parity) {
    asm volatile(
        "{\n\t.reg .pred P;\n"
        "W%=:\n\t"
        "mbarrier.try_wait.parity.shared.b64 P, [%0], %1;\n\t"
        "@!P bra W%=;\n\t}"
        :: "r"(bar), "r"(parity) : "memory");
}
#define FENCE_ASYNC() asm volatile("fence.proxy.async.shared::cta;" ::: "memory")

__device__ __forceinline__ void ldsm4(uint32_t* d, uint32_t addr) {
    asm volatile("ldmatrix.sync.aligned.m8n8.x4.shared.b16 {%0,%1,%2,%3}, [%4];"
                 : "=r"(d[0]), "=r"(d[1]), "=r"(d[2]), "=r"(d[3]) : "r"(addr));
}
__device__ __forceinline__ void mma16816(float* c, const uint32_t* a,
                                         uint32_t b0, uint32_t b1) {
    asm volatile(
        "mma.sync.aligned.m16n8k16.row.col.f32.f16.f16.f32 "
        "{%0,%1,%2,%3}, {%4,%5,%6,%7}, {%8,%9}, {%0,%1,%2,%3};"
        : "+f"(c[0]), "+f"(c[1]), "+f"(c[2]), "+f"(c[3])
        : "r"(a[0]), "r"(a[1]), "r"(a[2]), "r"(a[3]), "r"(b0), "r"(b1));
}

__device__ __forceinline__ float fexp2(float t) {
    t = fmaxf(t, -60.0f);
    float z = t + 12582912.0f;
    int   ki = __float_as_int(z);
    float n  = z - 12582912.0f;
    float f  = t - n;
    float p = 0.0013333558f;
    p = fmaf(p, f, 0.0096181291f);
    p = fmaf(p, f, 0.0555041087f);
    p = fmaf(p, f, 0.2402265070f);
    p = fmaf(p, f, 0.6931471806f);
    p = fmaf(p, f, 1.0f);
    return __int_as_float(__float_as_int(p) + (ki << 23));
}

// ============================ GEMM microkernel ============================
__device__ __forceinline__ void gemm_tile(uint32_t sbase, uint32_t mbar,
                                          const char* srcA, const char* srcB,
                                          int tid, int cnt[NSTAGE],
                                          float c[4][4][4]) {
    const int lane = tid & 31, warp = tid >> 5;
    const int mw = warp & 1, nw = warp >> 1;
    const int q2 = lane >> 3, r = lane & 7;
    const int kbh = (q2 >> 1) * 16;
    uint32_t aoff[4], boff[2];
    #pragma unroll
    for (int mt = 0; mt < 4; mt++)
        aoff[mt] = (uint32_t)((mw * 64 + mt * 16 + (q2 & 1) * 8 + r) * 128 + kbh);
    #pragma unroll
    for (int nb = 0; nb < 2; nb++)
        boff[nb] = (uint32_t)((nw * 32 + nb * 16 + (q2 & 1) * 8 + r) * 128 + kbh);

    if (tid == 0) {
        #pragma unroll
        for (int s = 0; s < NSTAGE; s++) {
            expect_tx(mbar + s * 8, 2 * BLK_BYTES);
            bulk_g2s(sbase + s * STAGE_BYTES,           srcA + s * BLK_BYTES,
                     BLK_BYTES, mbar + s * 8);
            bulk_g2s(sbase + s * STAGE_BYTES + A_BYTES, srcB + s * BLK_BYTES,
                     BLK_BYTES, mbar + s * 8);
        }
    }

    #pragma unroll 1
    for (int g = 0; g < NCH; g++) {
        int s = g % NSTAGE;
        bar_wait(mbar + s * 8, cnt[s] & 1);
        cnt[s]++;

        uint32_t sA = sbase + s * STAGE_BYTES;
        uint32_t sB = sA + A_BYTES;
        #pragma unroll
        for (int ks = 0; ks < 4; ks++) {
            int kd = ks * 32;
            uint32_t a[4][4], b[2][4];
            #pragma unroll
            for (int mt = 0; mt < 4; mt++) ldsm4(a[mt], sA + SWZ(aoff[mt] + kd));
            #pragma unroll
            for (int nb = 0; nb < 2; nb++) ldsm4(b[nb], sB + SWZ(boff[nb] + kd));
            #pragma unroll
            for (int mt = 0; mt < 4; mt++)
                #pragma unroll
                for (int nt = 0; nt < 4; nt++)
                    mma16816(c[mt][nt], a[mt],
                             b[nt >> 1][nt & 1], b[nt >> 1][(nt & 1) + 2]);
        }
        __syncthreads();
        if (tid == 0 && g + NSTAGE < NCH) {
            expect_tx(mbar + s * 8, 2 * BLK_BYTES);
            bulk_g2s(sA,           srcA + (size_t)(g + NSTAGE) * BLK_BYTES,
                     BLK_BYTES, mbar + s * 8);
            bulk_g2s(sA + A_BYTES, srcB + (size_t)(g + NSTAGE) * BLK_BYTES,
                     BLK_BYTES, mbar + s * 8);
        }
    }
}

__device__ __forceinline__ void mbar_setup(uint32_t mbar, int tid) {
    if (tid == 0) {
        #pragma unroll
        for (int s = 0; s < NSTAGE; s++) mbar_init(mbar + s * 8, 1);
        FENCE_ASYNC();
    }
    __syncthreads();
}

// fp16-blocked epilogue write (no bias)
__device__ __forceinline__ void epi_write(char* out, int rowtile, int coltile,
                                          int tid, float c[4][4][4]) {
    const int lane = tid & 31, warp = tid >> 5;
    const int mw = warp & 1, nw = warp >> 1;
    const int gq = lane >> 2, tg = lane & 3;
    #pragma unroll
    for (int mt = 0; mt < 4; mt++) {
        int rowL = mw * 64 + mt * 16 + gq;
        #pragma unroll
        for (int nt = 0; nt < 4; nt++) {
            int colL = nw * 32 + nt * 8 + 2 * tg;
            int col  = coltile * 128 + colL;
            float* cc = c[mt][nt];
            size_t blk = ((size_t)(rowtile * 16 + (col >> 6))) * BLK_BYTES;
            uint32_t cb = (uint32_t)((col & 63) * 2);
            *(__half2*)(out + blk + SWZ((uint32_t)( rowL      * 128) + cb)) =
                __floats2half2_rn(cc[0], cc[1]);
            *(__half2*)(out + blk + SWZ((uint32_t)((rowL + 8) * 128) + cb)) =
                __floats2half2_rn(cc[2], cc[3]);
        }
    }
}

// ============================ small kernels ============================
// transposed fp16 conversion: g_wT(i,o) = W[o,i], blocked layout
__global__ void conv_wT_kernel(const float* __restrict__ Wq,
                               const float* __restrict__ Wk) {
    int g = blockIdx.x * 256 + threadIdx.x;
    const float* src = (g < 131072) ? Wq : Wk;
    char* dst        = (g < 131072) ? (char*)g_wqT : (char*)g_wkT;
    int gm = g & 131071;
    int i  = gm & 1023;
    int ob = (gm >> 10) << 3;
    float v0 = src[(size_t)(ob + 0) * D + i];
    float v1 = src[(size_t)(ob + 1) * D + i];
    float v2 = src[(size_t)(ob + 2) * D + i];
    float v3 = src[(size_t)(ob + 3) * D + i];
    float v4 = src[(size_t)(ob + 4) * D + i];
    float v5 = src[(size_t)(ob + 5) * D + i];
    float v6 = src[(size_t)(ob + 6) * D + i];
    float v7 = src[(size_t)(ob + 7) * D + i];
    uint4 o;
    o.x = h2_bits(__floats2half2_rn(v0, v1));
    o.y = h2_bits(__floats2half2_rn(v2, v3));
    o.z = h2_bits(__floats2half2_rn(v4, v5));
    o.w = h2_bits(__floats2half2_rn(v6, v7));
    uint32_t inblk = SWZ((uint32_t)((i & 127) * 128 + (ob & 63) * 2));
    size_t byte = ((size_t)((i >> 7) * 16 + (ob >> 6))) * BLK_BYTES + inblk;
    *(uint4*)(dst + byte) = o;
}

__global__ void prep_u_kernel(const float* __restrict__ Wv,
                              const float* __restrict__ bv,
                              const float* __restrict__ Ww,
                              const float* __restrict__ Wk,
                              const float* __restrict__ bq) {
    if (blockIdx.x < 4) {                          // u = Ww @ Wv
        int e = blockIdx.x * 256 + threadIdx.x;
        float sum = 0.f;
        #pragma unroll 8
        for (int d = 0; d < D; d++) sum = fmaf(Ww[d], Wv[d * D + e], sum);
        g_u[e] = sum;
    } else if (blockIdx.x == 4) {                  // c = Ww·bv + counters
        __shared__ float red[256];
        float s = 0.f;
        for (int d = threadIdx.x; d < D; d += 256) s = fmaf(Ww[d], bv[d], s);
        red[threadIdx.x] = s;
        __syncthreads();
        for (int off = 128; off > 0; off >>= 1) {
            if (threadIdx.x < off) red[threadIdx.x] += red[threadIdx.x + off];
            __syncthreads();
        }
        if (threadIdx.x == 0) {
            g_c = red[0];
            g_ctr[0] = 0;
            g_ctr[1] = 0;
        }
    } else {                                       // cvec = bq @ Wk
        int e = (blockIdx.x - 5) * 256 + threadIdx.x;
        float sum = 0.f;
        #pragma unroll 8
        for (int d = 0; d < D; d++) sum = fmaf(bq[d], Wk[d * D + e], sum);
        g_cvec[e] = sum;
    }
}

// FUSED: x -> fp16 blocked conversion + s/c dot products, one x pass.
// One warp per row; lane handles float4 at col 4*(lane + 32*i).
__global__ void xprep_kernel(const float* __restrict__ x) {
    int row  = blockIdx.x * 8 + (threadIdx.x >> 5);
    int lane = threadIdx.x & 31;
    const float4* xr = (const float4*)(x + (size_t)row * D);
    const float4* u4 = (const float4*)g_u;
    const float4* c4 = (const float4*)g_cvec;
    char* xb = (char*)g_xb;
    size_t blkrow = ((size_t)(row >> 7)) * 16 * BLK_BYTES;
    uint32_t rb = (uint32_t)(row & 127) * 128;

    float su = 0.f, sc = 0.f;
    #pragma unroll
    for (int i = 0; i < 8; i++) {
        int f4 = lane + i * 32;            // float4 index, col = 4*f4
        float4 a = xr[f4];
        float4 b = u4[f4];
        float4 cv = c4[f4];
        su += a.x * b.x + a.y * b.y + a.z * b.z + a.w * b.w;
        sc += a.x * cv.x + a.y * cv.y + a.z * cv.z + a.w * cv.w;
        int col = f4 << 2;
        uint2 o;
        o.x = h2_bits(__floats2half2_rn(a.x, a.y));
        o.y = h2_bits(__floats2half2_rn(a.z, a.w));
        size_t byte = blkrow + (size_t)(col >> 6) * BLK_BYTES
                    + SWZ(rb + (uint32_t)((col & 63) * 2));
        *(uint2*)(xb + byte) = o;
    }
    #pragma unroll
    for (int off = 16; off > 0; off >>= 1) {
        su += __shfl_xor_sync(0xffffffffu, su, off);
        sc += __shfl_xor_sync(0xffffffffu, sc, off);
    }
    if (lane == 0)
        g_sc[row] = make_float2(su + g_c, sc * CLOGF - 4.0f);
}

// ============================ Mt GEMM ============================
__global__ __launch_bounds__(256, 2)
void mgemm_kernel() {
    extern __shared__ char dsm[];
    __shared__ __align__(8) uint64_t s_bar[NSTAGE];
    const int tid = threadIdx.x;
    uint32_t sbase = (smem_u32(dsm) + 1023u) & ~1023u;
    uint32_t mbar  = smem_u32(s_bar);
    mbar_setup(mbar, tid);

    const int jt = blockIdx.x, it = blockIdx.y;
    float cacc[4][4][4];
    #pragma unroll
    for (int a = 0; a < 4; a++)
        #pragma unroll
        for (int b = 0; b < 4; b++)
            #pragma unroll
            for (int e = 0; e < 4; e++) cacc[a][b][e] = 0.f;

    int cnt[NSTAGE] = {0, 0, 0};
    gemm_tile(sbase, mbar,
              (const char*)g_wkT + (size_t)jt * 16 * BLK_BYTES,
              (const char*)g_wqT + (size_t)it * 16 * BLK_BYTES,
              tid, cnt, cacc);
    epi_write((char*)g_mt, jt, it, tid, cacc);
}

// ============================ y projection ============================
__global__ __launch_bounds__(256, 2)
void proj_kernel() {
    extern __shared__ char dsm[];
    __shared__ __align__(8) uint64_t s_bar[NSTAGE];
    __shared__ int s_tile;

    const int tid  = threadIdx.x;
    uint32_t sbase = (smem_u32(dsm) + 1023u) & ~1023u;
    uint32_t mbar  = smem_u32(s_bar);
    mbar_setup(mbar, tid);
    int cnt[NSTAGE] = {0, 0, 0};

    for (;;) {
        __syncthreads();
        if (tid == 0) s_tile = (int)atomicAdd(&g_ctr[0], 1u);
        __syncthreads();
        int t = s_tile;
        if (t >= NPROJ_TILES) break;
        int ct = t >> 6;
        int rt = t & 63;

        float cacc[4][4][4];
        #pragma unroll
        for (int a = 0; a < 4; a++)
            #pragma unroll
            for (int b = 0; b < 4; b++)
                #pragma unroll
                for (int e = 0; e < 4; e++) cacc[a][b][e] = 0.f;

        gemm_tile(sbase, mbar,
                  (const char*)g_xb + (size_t)rt * 16 * BLK_BYTES,
                  (const char*)g_mt + (size_t)ct * 16 * BLK_BYTES,
                  tid, cnt, cacc);
        epi_write((char*)g_y, rt, ct, tid, cacc);
    }
}

// ============================ attention kernel ============================
__global__ __launch_bounds__(256, 2)
void attn_kernel() {
    extern __shared__ char dsm[];
    __shared__ __align__(8) uint64_t s_bar[NSTAGE];
    __shared__ float2 s_sm[128];
    __shared__ float s_red[128][4][2];
    __shared__ int s_tile;

    const int tid  = threadIdx.x;
    uint32_t sbase = (smem_u32(dsm) + 1023u) & ~1023u;
    uint32_t mbar  = smem_u32(s_bar);
    mbar_setup(mbar, tid);

    const int lane = tid & 31, warp = tid >> 5;
    const int mw = warp & 1, nw = warp >> 1;
    const int gq = lane >> 2, tg = lane & 3;
    int cnt[NSTAGE] = {0, 0, 0};

    for (;;) {
        __syncthreads();
        if (tid == 0) s_tile = (int)atomicAdd(&g_ctr[1], 1u);
        __syncthreads();
        int t = s_tile;
        if (t >= NATTN_TILES) break;
        int b     = t >> 7;
        int rm    = t & 127;
        int split = rm >> 4;
        int nt_q  = rm & 15;
        const int row0 = b * NTOK + nt_q * 128;

        float num[4][2], den[4][2];
        #pragma unroll
        for (int mt = 0; mt < 4; mt++)
            #pragma unroll
            for (int h = 0; h < 2; h++) { num[mt][h] = 0.f; den[mt][h] = 0.f; }

        #pragma unroll 1
        for (int blk = 0; blk < 2; blk++) {
            const int kb = b * NTOK + split * 256 + blk * 128;
            if (tid < 128) s_sm[tid] = g_sc[kb + tid];
            // (gemm_tile's internal __syncthreads orders this)

            float cacc[4][4][4];
            #pragma unroll
            for (int a = 0; a < 4; a++)
                #pragma unroll
                for (int c = 0; c < 4; c++)
                    #pragma unroll
                    for (int e = 0; e < 4; e++) cacc[a][c][e] = 0.f;

            gemm_tile(sbase, mbar,
                      (const char*)g_y  + (size_t)(row0 >> 7) * 16 * BLK_BYTES,
                      (const char*)g_xb + (size_t)(kb   >> 7) * 16 * BLK_BYTES,
                      tid, cnt, cacc);

            #pragma unroll
            for (int mt = 0; mt < 4; mt++)
                #pragma unroll
                for (int nt = 0; nt < 4; nt++) {
                    int colL = nw * 32 + nt * 8 + 2 * tg;
                    float2 sv0 = s_sm[colL], sv1 = s_sm[colL + 1];
                    float* cc = cacc[mt][nt];
                    float e0 = fexp2(fmaf(cc[0], CLOGF, sv0.y));
                    float e1 = fexp2(fmaf(cc[1], CLOGF, sv1.y));
                    float e2 = fexp2(fmaf(cc[2], CLOGF, sv0.y));
                    float e3 = fexp2(fmaf(cc[3], CLOGF, sv1.y));
                    den[mt][0] += e0 + e1;
                    den[mt][1] += e2 + e3;
                    num[mt][0] = fmaf(e0, sv0.x, fmaf(e1, sv1.x, num[mt][0]));
                    num[mt][1] = fmaf(e2, sv0.x, fmaf(e3, sv1.x, num[mt][1]));
                }
            __syncthreads();
        }

        #pragma unroll
        for (int mt = 0; mt < 4; mt++)
            #pragma unroll
            for (int h = 0; h < 2; h++) {
                num[mt][h] += __shfl_xor_sync(0xffffffffu, num[mt][h], 1);
                num[mt][h] += __shfl_xor_sync(0xffffffffu, num[mt][h], 2);
                den[mt][h] += __shfl_xor_sync(0xffffffffu, den[mt][h], 1);
                den[mt][h] += __shfl_xor_sync(0xffffffffu, den[mt][h], 2);
            }
        if (tg == 0) {
            #pragma unroll
            for (int mt = 0; mt < 4; mt++)
                #pragma unroll
                for (int h = 0; h < 2; h++) {
                    int rowl = mw * 64 + mt * 16 + h * 8 + gq;
                    s_red[rowl][nw][0] = num[mt][h];
                    s_red[rowl][nw][1] = den[mt][h];
                }
        }
        __syncthreads();
        if (tid < 128) {
            float n = 0.f, d = 0.f;
            #pragma unroll
            for (int w = 0; w < 4; w++) { n += s_red[tid][w][0]; d += s_red[tid][w][1]; }
            g_part[(size_t)(row0 + tid) * NSPLIT + split] = make_float2(n, d);
        }
    }
}

// ============================ combine ============================
__global__ void combine_kernel(const float* __restrict__ bw,
                               float* __restrict__ out) {
    int row = blockIdx.x * 256 + threadIdx.x;
    float n = 0.f, d = 0.f;
    #pragma unroll
    for (int s = 0; s < NSPLIT; s++) {
        float2 p = g_part[(size_t)row * NSPLIT + s];
        n += p.x; d += p.y;
    }
    out[row] = n / d + bw[0];
}

// ============================ launcher ============================
extern "C" void kernel_launch(void* const* d_in, const int* in_sizes, int n_in,
                              void* d_out, int out_size) {
    const float* x  = (const float*)d_in[0];
    const float* Wq = (const float*)d_in[1];
    const float* bq = (const float*)d_in[2];
    const float* Wk = (const float*)d_in[3];
    const float* bk = (const float*)d_in[4];
    const float* Wv = (const float*)d_in[5];
    const float* bv = (const float*)d_in[6];
    const float* Ww = (const float*)d_in[7];
    const float* bw = (const float*)d_in[8];
    float* out = (float*)d_out;
    (void)bk;

    cudaFuncSetAttribute(mgemm_kernel,
        cudaFuncAttributeMaxDynamicSharedMemorySize, DSM);
    cudaFuncSetAttribute(proj_kernel,
        cudaFuncAttributeMaxDynamicSharedMemorySize, DSM);
    cudaFuncSetAttribute(attn_kernel,
        cudaFuncAttributeMaxDynamicSharedMemorySize, DSM);

    conv_wT_kernel<<<1024, 256>>>(Wq, Wk);
    prep_u_kernel<<<9, 256>>>(Wv, bv, Ww, Wk, bq);

    dim3 gm(8, 8);
    mgemm_kernel<<<gm, 256, DSM>>>();

    xprep_kernel<<<MTOT / 8, 256>>>(x);

    proj_kernel<<<PERSIST_CTAS, 256, DSM>>>();
    attn_kernel<<<PERSIST_CTAS, 256, DSM>>>();

    combine_kernel<<<MTOT / 256, 256>>>(bw, out);
}